// round 1
// baseline (speedup 1.0000x reference)
#include <cuda_runtime.h>
#include <math.h>

// Problem constants
#define T_TOKENS 1024
#define HID      2048
#define INTER    1024
#define NR       32      // routed experts
#define ETOT     40      // routed + zero experts
#define TOPK     4
#define MAXP     (T_TOKENS * TOPK)
#define RSF      1.0f

// ---------------- device scratch (static; no allocation allowed) ----------
__device__ int   g_topk_id[T_TOKENS][TOPK];   // routed id or -1
__device__ float g_topk_w [T_TOKENS][TOPK];
__device__ float g_zero_sum[T_TOKENS];
__device__ int   g_counts [NR];
__device__ int   g_offsets[NR + 1];
__device__ int   g_pair_tok[MAXP];
__device__ float g_pair_w [MAXP];
__device__ float g_h[(size_t)MAXP * INTER];   // 16 MB intermediate h = silu(g)*u

// ---------------- kernel 0: zero counters ---------------------------------
__global__ void zero_kernel() {
    int i = threadIdx.x;
    if (i < NR) g_counts[i] = 0;
}

// ---------------- kernel 1: router ----------------------------------------
// One block per token, 128 threads. 40 dot products of length 2048, then
// sigmoid + top-4 on (score + bias); routing weight = raw sigmoid score.
__global__ void __launch_bounds__(128) router_kernel(
    const float* __restrict__ x, const float* __restrict__ rw,
    const float* __restrict__ bias)
{
    int t = blockIdx.x;
    __shared__ float s_logit[ETOT];
    int tid = threadIdx.x;
    int warp = tid >> 5, lane = tid & 31;
    const float* xr = x + (size_t)t * HID;
    for (int e = warp; e < ETOT; e += 4) {
        const float* wr = rw + (size_t)e * HID;
        float acc = 0.f;
        #pragma unroll 4
        for (int j = lane; j < HID; j += 32) acc += xr[j] * wr[j];
        #pragma unroll
        for (int o = 16; o; o >>= 1) acc += __shfl_xor_sync(0xffffffffu, acc, o);
        if (lane == 0) s_logit[e] = acc;
    }
    __syncthreads();
    if (tid == 0) {
        float score[ETOT], sel[ETOT];
        for (int e = 0; e < ETOT; e++) {
            float s = 1.f / (1.f + expf(-s_logit[e]));
            score[e] = s;
            sel[e] = s + bias[e];
        }
        float zsum = 0.f;
        for (int k = 0; k < TOPK; k++) {
            int best = -1; float bv = -1e30f;
            for (int e = 0; e < ETOT; e++)
                if (sel[e] > bv) { bv = sel[e]; best = e; }
            sel[best] = -1e30f;
            if (best < NR) {
                g_topk_id[t][k] = best;
                g_topk_w[t][k]  = score[best];
                atomicAdd(&g_counts[best], 1);
            } else {
                g_topk_id[t][k] = -1;
                g_topk_w[t][k]  = 0.f;
                zsum += score[best];
            }
        }
        g_zero_sum[t] = zsum;
    }
}

// ---------------- kernel 2: exclusive scan of counts ----------------------
__global__ void scan_kernel() {
    if (threadIdx.x == 0) {
        int o = 0;
        for (int e = 0; e < NR; e++) { g_offsets[e] = o; o += g_counts[e]; }
        g_offsets[NR] = o;
    }
}

// ---------------- kernel 3: deterministic compaction ----------------------
// Block e scans all 1024 tokens; position = exclusive prefix sum of the
// selection flags (token order), so the pair list is fully deterministic.
__global__ void __launch_bounds__(1024) scatter_kernel() {
    int e = blockIdx.x;
    int t = threadIdx.x;
    float w = 0.f; int flag = 0;
    #pragma unroll
    for (int k = 0; k < TOPK; k++)
        if (g_topk_id[t][k] == e) { flag = 1; w = g_topk_w[t][k]; }

    __shared__ int warp_sums[32];
    int lane = t & 31, wid = t >> 5;
    int v = flag;
    #pragma unroll
    for (int o = 1; o < 32; o <<= 1) {
        int n = __shfl_up_sync(0xffffffffu, v, o);
        if (lane >= o) v += n;
    }
    if (lane == 31) warp_sums[wid] = v;
    __syncthreads();
    if (wid == 0) {
        int s = warp_sums[lane];
        #pragma unroll
        for (int o = 1; o < 32; o <<= 1) {
            int n = __shfl_up_sync(0xffffffffu, s, o);
            if (lane >= o) s += n;
        }
        warp_sums[lane] = s;
    }
    __syncthreads();
    int incl = v + (wid > 0 ? warp_sums[wid - 1] : 0);
    if (flag) {
        int idx = g_offsets[e] + incl - 1;
        g_pair_tok[idx] = t;
        g_pair_w[idx]   = w;
    }
}

// ---------------- kernel 4: output init with zero-expert term -------------
__global__ void init_out_kernel(const float* __restrict__ x, float* __restrict__ out) {
    int idx = blockIdx.x * 256 + threadIdx.x;
    int t = idx >> 11;  // / HID
    out[idx] = x[idx] * g_zero_sum[t] * RSF;
}

// ---------------- kernel 5: stage 1 gather-GEMM (gate+up fused) -----------
// Per block: 64 gathered tokens x 128 inter cols, K=2048, BK=16.
// Computes g and u simultaneously, h = silu(g)*u to g_h.
__global__ void __launch_bounds__(256) stage1_kernel(
    const float* __restrict__ x,
    const float* __restrict__ w1g, const float* __restrict__ w1u)
{
    int e  = blockIdx.y >> 4;
    int mt = blockIdx.y & 15;
    int off = g_offsets[e];
    int cnt = g_offsets[e + 1] - off;
    int m0 = mt * 64;
    if (m0 >= cnt) return;
    int i0 = blockIdx.x * 128;

    __shared__ __align__(16) float Xs[16][68];
    __shared__ __align__(16) float Gs[16][132];
    __shared__ __align__(16) float Us[16][132];
    __shared__ int s_tok[64];

    int tid = threadIdx.x;
    if (tid < 64) {
        int m = m0 + tid;
        s_tok[tid] = (m < cnt) ? g_pair_tok[off + m] : -1;
    }
    __syncthreads();

    float accG[4][8], accU[4][8];
    #pragma unroll
    for (int a = 0; a < 4; a++)
        #pragma unroll
        for (int b = 0; b < 8; b++) { accG[a][b] = 0.f; accU[a][b] = 0.f; }

    int ty = tid >> 4, tx = tid & 15;  // rows m=ty*4.., cols i=tx*8..
    const float* wg_base = w1g + ((size_t)e * INTER + i0) * HID;
    const float* wu_base = w1u + ((size_t)e * INTER + i0) * HID;

    for (int k0 = 0; k0 < HID; k0 += 16) {
        #pragma unroll
        for (int r = 0; r < 4; r++) {
            int idx = tid + r * 256;
            int row = idx >> 4, kk = idx & 15;
            int tok = s_tok[row];
            Xs[kk][row] = (tok >= 0) ? x[(size_t)tok * HID + k0 + kk] : 0.f;
        }
        #pragma unroll
        for (int r = 0; r < 8; r++) {
            int idx = tid + r * 256;
            int row = idx >> 4, kk = idx & 15;
            size_t go = (size_t)row * HID + k0 + kk;
            Gs[kk][row] = wg_base[go];
            Us[kk][row] = wu_base[go];
        }
        __syncthreads();
        #pragma unroll
        for (int kk = 0; kk < 16; kk++) {
            float4 xv = *reinterpret_cast<const float4*>(&Xs[kk][ty * 4]);
            float4 g0 = *reinterpret_cast<const float4*>(&Gs[kk][tx * 8]);
            float4 g1 = *reinterpret_cast<const float4*>(&Gs[kk][tx * 8 + 4]);
            float4 u0 = *reinterpret_cast<const float4*>(&Us[kk][tx * 8]);
            float4 u1 = *reinterpret_cast<const float4*>(&Us[kk][tx * 8 + 4]);
            float xa[4] = {xv.x, xv.y, xv.z, xv.w};
            float ga[8] = {g0.x, g0.y, g0.z, g0.w, g1.x, g1.y, g1.z, g1.w};
            float ua[8] = {u0.x, u0.y, u0.z, u0.w, u1.x, u1.y, u1.z, u1.w};
            #pragma unroll
            for (int mm = 0; mm < 4; mm++)
                #pragma unroll
                for (int nn = 0; nn < 8; nn++) {
                    accG[mm][nn] += xa[mm] * ga[nn];
                    accU[mm][nn] += xa[mm] * ua[nn];
                }
        }
        __syncthreads();
    }

    #pragma unroll
    for (int mm = 0; mm < 4; mm++) {
        int m = m0 + ty * 4 + mm;
        if (m < cnt) {
            float* hrow = g_h + (size_t)(off + m) * INTER + i0;
            #pragma unroll
            for (int nn = 0; nn < 8; nn++) {
                float g = accG[mm][nn];
                float u = accU[mm][nn];
                float s = g / (1.f + expf(-g));   // silu
                hrow[tx * 8 + nn] = s * u;
            }
        }
    }
}

// ---------------- kernel 6: stage 2 GEMM + weighted combine ---------------
// Per block: 64 pairs x 128 hidden cols, K=INTER=1024, BK=16.
// Epilogue: atomicAdd(out[t], w_pair * acc * RSF).
__global__ void __launch_bounds__(256) stage2_kernel(
    const float* __restrict__ w2, float* __restrict__ out)
{
    int e  = blockIdx.y >> 4;
    int mt = blockIdx.y & 15;
    int off = g_offsets[e];
    int cnt = g_offsets[e + 1] - off;
    int m0 = mt * 64;
    if (m0 >= cnt) return;
    int n0 = blockIdx.x * 128;

    __shared__ __align__(16) float Hs[16][68];
    __shared__ __align__(16) float Ws[16][132];
    __shared__ int   s_tok[64];
    __shared__ float s_w[64];

    int tid = threadIdx.x;
    if (tid < 64) {
        int m = m0 + tid;
        if (m < cnt) { s_tok[tid] = g_pair_tok[off + m]; s_w[tid] = g_pair_w[off + m]; }
        else         { s_tok[tid] = -1;                  s_w[tid] = 0.f; }
    }
    __syncthreads();

    float acc[4][8];
    #pragma unroll
    for (int a = 0; a < 4; a++)
        #pragma unroll
        for (int b = 0; b < 8; b++) acc[a][b] = 0.f;

    int ty = tid >> 4, tx = tid & 15;
    const float* w2b = w2 + ((size_t)e * HID + n0) * INTER;

    for (int k0 = 0; k0 < INTER; k0 += 16) {
        #pragma unroll
        for (int r = 0; r < 4; r++) {
            int idx = tid + r * 256;
            int row = idx >> 4, kk = idx & 15;
            int m = m0 + row;
            Hs[kk][row] = (m < cnt) ? g_h[(size_t)(off + m) * INTER + k0 + kk] : 0.f;
        }
        #pragma unroll
        for (int r = 0; r < 8; r++) {
            int idx = tid + r * 256;
            int row = idx >> 4, kk = idx & 15;
            Ws[kk][row] = w2b[(size_t)row * INTER + k0 + kk];
        }
        __syncthreads();
        #pragma unroll
        for (int kk = 0; kk < 16; kk++) {
            float4 hv = *reinterpret_cast<const float4*>(&Hs[kk][ty * 4]);
            float4 w0 = *reinterpret_cast<const float4*>(&Ws[kk][tx * 8]);
            float4 w1 = *reinterpret_cast<const float4*>(&Ws[kk][tx * 8 + 4]);
            float ha[4] = {hv.x, hv.y, hv.z, hv.w};
            float wa[8] = {w0.x, w0.y, w0.z, w0.w, w1.x, w1.y, w1.z, w1.w};
            #pragma unroll
            for (int mm = 0; mm < 4; mm++)
                #pragma unroll
                for (int nn = 0; nn < 8; nn++)
                    acc[mm][nn] += ha[mm] * wa[nn];
        }
        __syncthreads();
    }

    #pragma unroll
    for (int mm = 0; mm < 4; mm++) {
        int m = m0 + ty * 4 + mm;
        if (m < cnt) {
            int   t  = s_tok[ty * 4 + mm];
            float pw = s_w[ty * 4 + mm] * RSF;
            float* orow = out + (size_t)t * HID + n0;
            #pragma unroll
            for (int nn = 0; nn < 8; nn++)
                atomicAdd(&orow[tx * 8 + nn], pw * acc[mm][nn]);
        }
    }
}

// ---------------- launch ---------------------------------------------------
extern "C" void kernel_launch(void* const* d_in, const int* in_sizes, int n_in,
                              void* d_out, int out_size)
{
    const float* x    = (const float*)d_in[0];   // [1024, 2048]
    const float* rw   = (const float*)d_in[1];   // [40, 2048]
    const float* bias = (const float*)d_in[2];   // [40]
    const float* w1g  = (const float*)d_in[3];   // [32, 1024, 2048]
    const float* w1u  = (const float*)d_in[4];   // [32, 1024, 2048]
    const float* w2   = (const float*)d_in[5];   // [32, 2048, 1024]
    float* out = (float*)d_out;                  // [1024, 2048]

    zero_kernel<<<1, 32>>>();
    router_kernel<<<T_TOKENS, 128>>>(x, rw, bias);
    scan_kernel<<<1, 32>>>();
    scatter_kernel<<<NR, 1024>>>();
    init_out_kernel<<<(T_TOKENS * HID) / 256, 256>>>(x, out);
    stage1_kernel<<<dim3(INTER / 128, NR * 16), 256>>>(x, w1g, w1u);
    stage2_kernel<<<dim3(HID / 128, NR * 16), 256>>>(w2, out);
}

// round 5
// speedup vs baseline: 3.4113x; 3.4113x over previous
#include <cuda_runtime.h>
#include <cstdint>
#include <math.h>

// Problem constants
#define T_TOKENS 1024
#define HID      2048
#define INTER    1024
#define NR       32
#define ETOT     40
#define TOPK     4
#define MAXP     (T_TOKENS * TOPK)
#define RSF      1.0f

#define CH1      (HID / 32)     // 64 K-chunks in stage 1 (chunk K = 32)
#define CH2      (INTER / 32)   // 32 K-chunks in stage 2
#define SMEM_SZ  66560          // 1KB meta + buffers

// Compensation for HW mantissa truncation of the raw-fp32 weight operand:
// mean relative truncation error = 2^-11 * E[1/m] (m log-uniform) = 3.522e-4.
#define COMP 1.0003522f

// ---------------- device scratch ------------------------------------------
__device__ int   g_topk_id[T_TOKENS][TOPK];
__device__ float g_topk_w [T_TOKENS][TOPK];
__device__ float g_zero_sum[T_TOKENS];
__device__ int   g_counts [NR];
__device__ int   g_offsets[NR + 1];
__device__ int   g_pair_tok[MAXP];
__device__ float g_pair_w [MAXP];
__device__ int   g_tok_pair[T_TOKENS][TOPK];
__device__ __align__(16) float g_xc[(size_t)T_TOKENS * HID];   // tf32(x*COMP), 8MB
__device__ __align__(16) float g_h [(size_t)MAXP * INTER];     // 16 MB, tf32(h*COMP)
__device__ __align__(16) float g_ye[(size_t)MAXP * HID];       // 33.5 MB weighted ye

// ---------------- helpers --------------------------------------------------
__device__ __forceinline__ float f2tf32c(float x) {
    uint32_t o;
    float xs = x * COMP;
    asm("cvt.rna.tf32.f32 %0, %1;" : "=r"(o) : "f"(xs));
    return __uint_as_float(o);
}

__device__ __forceinline__ void mma_tf32(float* d, const float4& a, const float2& b) {
    asm volatile(
        "mma.sync.aligned.m16n8k8.row.col.f32.tf32.tf32.f32 "
        "{%0,%1,%2,%3}, {%4,%5,%6,%7}, {%8,%9}, {%0,%1,%2,%3};"
        : "+f"(d[0]), "+f"(d[1]), "+f"(d[2]), "+f"(d[3])
        : "r"(__float_as_uint(a.x)), "r"(__float_as_uint(a.y)),
          "r"(__float_as_uint(a.z)), "r"(__float_as_uint(a.w)),
          "r"(__float_as_uint(b.x)), "r"(__float_as_uint(b.y)));
}

// ---------------- kernel 0: zero state ------------------------------------
__global__ void zero_kernel() {
    int i = blockIdx.x * 256 + threadIdx.x;
    ((int*)g_tok_pair)[i] = -1;
    if (i < NR) g_counts[i] = 0;
}

// ---------------- kernel 0b: preconvert activations -----------------------
__global__ void conv_x_kernel(const float* __restrict__ x) {
    int i = (blockIdx.x * 256 + threadIdx.x) * 4;
    float4 v = *(const float4*)(x + i);
    v.x = f2tf32c(v.x); v.y = f2tf32c(v.y);
    v.z = f2tf32c(v.z); v.w = f2tf32c(v.w);
    *(float4*)(g_xc + i) = v;
}

// ---------------- kernel 1: router (fp32) ---------------------------------
__global__ void __launch_bounds__(128) router_kernel(
    const float* __restrict__ x, const float* __restrict__ rw,
    const float* __restrict__ bias)
{
    int t = blockIdx.x;
    __shared__ float s_logit[ETOT];
    int tid = threadIdx.x;
    int warp = tid >> 5, lane = tid & 31;
    const float* xr = x + (size_t)t * HID;
    for (int e = warp; e < ETOT; e += 4) {
        const float* wr = rw + (size_t)e * HID;
        float acc = 0.f;
        #pragma unroll 4
        for (int j = lane; j < HID; j += 32) acc += xr[j] * wr[j];
        #pragma unroll
        for (int o = 16; o; o >>= 1) acc += __shfl_xor_sync(0xffffffffu, acc, o);
        if (lane == 0) s_logit[e] = acc;
    }
    __syncthreads();
    if (tid == 0) {
        float score[ETOT], sel[ETOT];
        for (int e = 0; e < ETOT; e++) {
            float s = 1.f / (1.f + expf(-s_logit[e]));
            score[e] = s;
            sel[e] = s + bias[e];
        }
        float zsum = 0.f;
        for (int k = 0; k < TOPK; k++) {
            int best = -1; float bv = -1e30f;
            for (int e = 0; e < ETOT; e++)
                if (sel[e] > bv) { bv = sel[e]; best = e; }
            sel[best] = -1e30f;
            if (best < NR) {
                g_topk_id[t][k] = best;
                g_topk_w[t][k]  = score[best];
                atomicAdd(&g_counts[best], 1);
            } else {
                g_topk_id[t][k] = -1;
                g_topk_w[t][k]  = 0.f;
                zsum += score[best];
            }
        }
        g_zero_sum[t] = zsum;
    }
}

// ---------------- kernel 2: scan ------------------------------------------
__global__ void scan_kernel() {
    if (threadIdx.x == 0) {
        int o = 0;
        for (int e = 0; e < NR; e++) { g_offsets[e] = o; o += g_counts[e]; }
        g_offsets[NR] = o;
    }
}

// ---------------- kernel 3: deterministic compaction ----------------------
__global__ void __launch_bounds__(1024) scatter_kernel() {
    int e = blockIdx.x;
    int t = threadIdx.x;
    float w = 0.f; int flag = 0; int kmatch = 0;
    #pragma unroll
    for (int k = 0; k < TOPK; k++)
        if (g_topk_id[t][k] == e) { flag = 1; w = g_topk_w[t][k]; kmatch = k; }

    __shared__ int warp_sums[32];
    int lane = t & 31, wid = t >> 5;
    int v = flag;
    #pragma unroll
    for (int o = 1; o < 32; o <<= 1) {
        int n = __shfl_up_sync(0xffffffffu, v, o);
        if (lane >= o) v += n;
    }
    if (lane == 31) warp_sums[wid] = v;
    __syncthreads();
    if (wid == 0) {
        int s = warp_sums[lane];
        #pragma unroll
        for (int o = 1; o < 32; o <<= 1) {
            int n = __shfl_up_sync(0xffffffffu, s, o);
            if (lane >= o) s += n;
        }
        warp_sums[lane] = s;
    }
    __syncthreads();
    int incl = v + (wid > 0 ? warp_sums[wid - 1] : 0);
    if (flag) {
        int idx = g_offsets[e] + incl - 1;
        g_pair_tok[idx] = t;
        g_pair_w[idx]   = w;
        g_tok_pair[t][kmatch] = idx;
    }
}

// ============ smem fragment-layout addressing ==============================
// A tile (128 rows x 32 k): frag addr = ((mt*4+s)*32 + l)*4 + j  (floats)
//   element (r=row%16, kk): s=kk/8, l=(r%8)*4 + kk%4, j=2*((kk%8)/4) + r/8
//   compute: thread lane reads float4 at ((mt*4+s)*32+lane)*4 -> {a0,a1,a2,a3}
// B tile (Nt rows x 32 k): frag addr = ((nt*4+s)*32 + l)*2 + j
//   element (n, kk): nt=n/8, s=kk/8, l=(n%8)*4 + kk%4, j=(kk%8)/4
//   compute: lane reads float2 at ((nt*4+s)*32+lane)*2 -> {b0,b1}

// ---------------- kernel 4: stage 1 (x @ w1g, x @ w1up, SwiGLU) ------------
// CTA tile: 128 gathered tokens x 64 inter cols; warps 4(m) x 2(n).
__global__ void __launch_bounds__(256) stage1_kernel(
    const float* __restrict__ w1g, const float* __restrict__ w1u)
{
    int e   = blockIdx.y;
    int off = g_offsets[e];
    int cnt = g_offsets[e + 1] - off;
    int m0  = blockIdx.z * 128;
    if (m0 >= cnt) return;
    int i0 = blockIdx.x * 64;

    extern __shared__ __align__(16) char smem[];
    int*   s_tok = (int*)smem;
    float* sA = (float*)(smem + 1024);                    // 2 x 4096 floats
    float* sG = (float*)(smem + 1024 + 32768);            // 2 x 2048 floats
    float* sU = (float*)(smem + 1024 + 32768 + 16384);    // 2 x 2048 floats

    int tid = threadIdx.x, lane = tid & 31, wid = tid >> 5;
    if (tid < 128) {
        int m = m0 + tid;
        s_tok[tid] = (m < cnt) ? g_pair_tok[off + m] : -1;
    }
    __syncthreads();

    const float* gbase = w1g + ((size_t)e * INTER + i0) * HID;
    const float* ubase = w1u + ((size_t)e * INTER + i0) * HID;

    float accG[2][4][4], accU[2][4][4];
    #pragma unroll
    for (int a = 0; a < 2; a++)
        #pragma unroll
        for (int b = 0; b < 4; b++)
            #pragma unroll
            for (int c = 0; c < 4; c++) { accG[a][b][c] = 0.f; accU[a][b][c] = 0.f; }

    float4 ra[4], rg[2], ru[2];

    auto ldg_chunk = [&](int it) {
        int k0 = it * 32;
        #pragma unroll
        for (int i = 0; i < 4; i++) {
            int idx = tid + i * 256; int r = idx >> 3, q = idx & 7;
            int tok = s_tok[r];
            ra[i] = (tok >= 0) ? *(const float4*)(g_xc + (size_t)tok * HID + k0 + q * 4)
                               : make_float4(0.f, 0.f, 0.f, 0.f);
        }
        #pragma unroll
        for (int i = 0; i < 2; i++) {
            int idx = tid + i * 256; int r = idx >> 3, q = idx & 7;
            size_t go = (size_t)r * HID + k0 + q * 4;
            rg[i] = *(const float4*)(gbase + go);
            ru[i] = *(const float4*)(ubase + go);
        }
    };
    auto sts_chunk = [&](int buf) {
        float* A = sA + buf * 4096;
        float* G = sG + buf * 2048;
        float* U = sU + buf * 2048;
        #pragma unroll
        for (int i = 0; i < 4; i++) {
            int idx = tid + i * 256; int r = idx >> 3, q = idx & 7;
            int mt = r >> 4, rr = r & 15, s = q >> 1;
            int j = ((q & 1) << 1) | (rr >> 3);
            float* pa = A + (((mt * 4 + s) * 32 + (rr & 7) * 4) << 2) + j;
            pa[0] = ra[i].x; pa[4] = ra[i].y; pa[8] = ra[i].z; pa[12] = ra[i].w;
        }
        #pragma unroll
        for (int i = 0; i < 2; i++) {
            int idx = tid + i * 256; int r = idx >> 3, q = idx & 7;
            int nt = r >> 3, nr = r & 7, s = q >> 1, j = q & 1;
            int base = (((nt * 4 + s) * 32 + nr * 4) << 1) + j;
            float* pg = G + base;
            pg[0] = rg[i].x; pg[2] = rg[i].y; pg[4] = rg[i].z; pg[6] = rg[i].w;
            float* pu = U + base;
            pu[0] = ru[i].x; pu[2] = ru[i].y; pu[4] = ru[i].z; pu[6] = ru[i].w;
        }
    };
    int wm = wid >> 1, wn = wid & 1;
    auto compute = [&](int buf) {
        float* A = sA + buf * 4096;
        float* G = sG + buf * 2048;
        float* U = sU + buf * 2048;
        #pragma unroll
        for (int s = 0; s < 4; s++) {
            float4 a0 = *(float4*)(A + ((((wm * 2)     * 4 + s) * 32 + lane) << 2));
            float4 a1 = *(float4*)(A + ((((wm * 2 + 1) * 4 + s) * 32 + lane) << 2));
            #pragma unroll
            for (int t = 0; t < 4; t++) {
                int bo = ((((wn * 4 + t) * 4 + s) * 32 + lane) << 1);
                float2 bg = *(float2*)(G + bo);
                float2 bu = *(float2*)(U + bo);
                mma_tf32(accG[0][t], a0, bg);
                mma_tf32(accG[1][t], a1, bg);
                mma_tf32(accU[0][t], a0, bu);
                mma_tf32(accU[1][t], a1, bu);
            }
        }
    };

    ldg_chunk(0); sts_chunk(0);
    __syncthreads();
    for (int it = 0; it < CH1; ++it) {
        bool pf = (it + 1) < CH1;
        if (pf) ldg_chunk(it + 1);
        compute(it & 1);
        if (pf) sts_chunk((it + 1) & 1);
        __syncthreads();
    }

    // epilogue: h = silu(g)*u, tf32-round with COMP (for stage-2 A operand)
    #pragma unroll
    for (int mi = 0; mi < 2; mi++) {
        int rbase = wm * 32 + mi * 16 + (lane >> 2);
        #pragma unroll
        for (int t = 0; t < 4; t++) {
            int col = i0 + wn * 32 + t * 8 + (lane & 3) * 2;
            #pragma unroll
            for (int half = 0; half < 2; half++) {
                int rloc = rbase + half * 8;
                int m = m0 + rloc;
                if (m < cnt) {
                    float g0 = accG[mi][t][half * 2],     u0 = accU[mi][t][half * 2];
                    float g1 = accG[mi][t][half * 2 + 1], u1 = accU[mi][t][half * 2 + 1];
                    float2 o;
                    o.x = f2tf32c((g0 / (1.f + __expf(-g0))) * u0);
                    o.y = f2tf32c((g1 / (1.f + __expf(-g1))) * u1);
                    *(float2*)(g_h + (size_t)(off + m) * INTER + col) = o;
                }
            }
        }
    }
}

// ---------------- kernel 5: stage 2 (h @ w2, weighted) ---------------------
// CTA tile: 128 pairs x 128 hidden cols; warps 4(m) x 2(n).
__global__ void __launch_bounds__(256) stage2_kernel(const float* __restrict__ w2)
{
    int e   = blockIdx.y;
    int off = g_offsets[e];
    int cnt = g_offsets[e + 1] - off;
    int m0  = blockIdx.z * 128;
    if (m0 >= cnt) return;
    int n0 = blockIdx.x * 128;

    extern __shared__ __align__(16) char smem[];
    float* s_w = (float*)(smem + 512);
    float* sA = (float*)(smem + 1024);            // 2 x 4096 floats
    float* sB = (float*)(smem + 1024 + 32768);    // 2 x 4096 floats

    int tid = threadIdx.x, lane = tid & 31, wid = tid >> 5;
    if (tid < 128) {
        int m = m0 + tid;
        s_w[tid] = (m < cnt) ? g_pair_w[off + m] : 0.f;
    }
    __syncthreads();

    const float* bbase = w2 + ((size_t)e * HID + n0) * INTER;

    float acc[2][8][4];
    #pragma unroll
    for (int a = 0; a < 2; a++)
        #pragma unroll
        for (int b = 0; b < 8; b++)
            #pragma unroll
            for (int c = 0; c < 4; c++) acc[a][b][c] = 0.f;

    float4 ra[4], rb[4];
    auto ldg_chunk = [&](int it) {
        int k0 = it * 32;
        #pragma unroll
        for (int i = 0; i < 4; i++) {
            int idx = tid + i * 256; int r = idx >> 3, q = idx & 7;
            int m = m0 + r;
            ra[i] = (m < cnt) ? *(const float4*)(g_h + (size_t)(off + m) * INTER + k0 + q * 4)
                              : make_float4(0.f, 0.f, 0.f, 0.f);
            rb[i] = *(const float4*)(bbase + (size_t)r * INTER + k0 + q * 4);
        }
    };
    auto sts_chunk = [&](int buf) {
        float* A = sA + buf * 4096;
        float* B = sB + buf * 4096;
        #pragma unroll
        for (int i = 0; i < 4; i++) {
            int idx = tid + i * 256; int r = idx >> 3, q = idx & 7;
            int mt = r >> 4, rr = r & 15, s = q >> 1;
            int j = ((q & 1) << 1) | (rr >> 3);
            float* pa = A + (((mt * 4 + s) * 32 + (rr & 7) * 4) << 2) + j;
            pa[0] = ra[i].x; pa[4] = ra[i].y; pa[8] = ra[i].z; pa[12] = ra[i].w;
            int nt = r >> 3, nr = r & 7, jb = q & 1;
            float* pb = B + (((nt * 4 + s) * 32 + nr * 4) << 1) + jb;
            pb[0] = rb[i].x; pb[2] = rb[i].y; pb[4] = rb[i].z; pb[6] = rb[i].w;
        }
    };
    int wm = wid >> 1, wn = wid & 1;
    auto compute = [&](int buf) {
        float* A = sA + buf * 4096;
        float* B = sB + buf * 4096;
        #pragma unroll
        for (int s = 0; s < 4; s++) {
            float4 a0 = *(float4*)(A + ((((wm * 2)     * 4 + s) * 32 + lane) << 2));
            float4 a1 = *(float4*)(A + ((((wm * 2 + 1) * 4 + s) * 32 + lane) << 2));
            #pragma unroll
            for (int t = 0; t < 8; t++) {
                float2 b = *(float2*)(B + ((((wn * 8 + t) * 4 + s) * 32 + lane) << 1));
                mma_tf32(acc[0][t], a0, b);
                mma_tf32(acc[1][t], a1, b);
            }
        }
    };

    ldg_chunk(0); sts_chunk(0);
    __syncthreads();
    for (int it = 0; it < CH2; ++it) {
        bool pf = (it + 1) < CH2;
        if (pf) ldg_chunk(it + 1);
        compute(it & 1);
        if (pf) sts_chunk((it + 1) & 1);
        __syncthreads();
    }

    // epilogue: weighted rows into g_ye
    #pragma unroll
    for (int mi = 0; mi < 2; mi++) {
        int rbase = wm * 32 + mi * 16 + (lane >> 2);
        #pragma unroll
        for (int t = 0; t < 8; t++) {
            int col = n0 + wn * 64 + t * 8 + (lane & 3) * 2;
            #pragma unroll
            for (int half = 0; half < 2; half++) {
                int rloc = rbase + half * 8;
                int m = m0 + rloc;
                if (m < cnt) {
                    float pw = s_w[rloc];
                    float2 o;
                    o.x = pw * acc[mi][t][half * 2];
                    o.y = pw * acc[mi][t][half * 2 + 1];
                    *(float2*)(g_ye + (size_t)(off + m) * HID + col) = o;
                }
            }
        }
    }
}

// ---------------- kernel 6: combine ---------------------------------------
__global__ void __launch_bounds__(256) combine_kernel(
    const float* __restrict__ x, float* __restrict__ out)
{
    int t = blockIdx.x;
    int c = threadIdx.x * 8;
    float zs = g_zero_sum[t];
    const float* xr = x + (size_t)t * HID + c;
    float4 a0 = *(const float4*)xr;
    float4 a1 = *(const float4*)(xr + 4);
    a0.x *= zs; a0.y *= zs; a0.z *= zs; a0.w *= zs;
    a1.x *= zs; a1.y *= zs; a1.z *= zs; a1.w *= zs;
    #pragma unroll
    for (int k = 0; k < TOPK; k++) {
        int p = g_tok_pair[t][k];
        if (p >= 0) {
            const float* yr = g_ye + (size_t)p * HID + c;
            float4 y0 = *(const float4*)yr;
            float4 y1 = *(const float4*)(yr + 4);
            a0.x += y0.x; a0.y += y0.y; a0.z += y0.z; a0.w += y0.w;
            a1.x += y1.x; a1.y += y1.y; a1.z += y1.z; a1.w += y1.w;
        }
    }
    a0.x *= RSF; a0.y *= RSF; a0.z *= RSF; a0.w *= RSF;
    a1.x *= RSF; a1.y *= RSF; a1.z *= RSF; a1.w *= RSF;
    float* o = out + (size_t)t * HID + c;
    *(float4*)o = a0;
    *(float4*)(o + 4) = a1;
}

// ---------------- launch ---------------------------------------------------
extern "C" void kernel_launch(void* const* d_in, const int* in_sizes, int n_in,
                              void* d_out, int out_size)
{
    const float* x    = (const float*)d_in[0];
    const float* rw   = (const float*)d_in[1];
    const float* bias = (const float*)d_in[2];
    const float* w1g  = (const float*)d_in[3];
    const float* w1u  = (const float*)d_in[4];
    const float* w2   = (const float*)d_in[5];
    float* out = (float*)d_out;

    cudaFuncSetAttribute(stage1_kernel, cudaFuncAttributeMaxDynamicSharedMemorySize, SMEM_SZ);
    cudaFuncSetAttribute(stage2_kernel, cudaFuncAttributeMaxDynamicSharedMemorySize, SMEM_SZ);

    zero_kernel<<<16, 256>>>();
    conv_x_kernel<<<(T_TOKENS * HID) / (256 * 4), 256>>>(x);
    router_kernel<<<T_TOKENS, 128>>>(x, rw, bias);
    scan_kernel<<<1, 32>>>();
    scatter_kernel<<<NR, 1024>>>();
    stage1_kernel<<<dim3(INTER / 64, NR, 8), 256, SMEM_SZ>>>(w1g, w1u);
    stage2_kernel<<<dim3(HID / 128, NR, 8), 256, SMEM_SZ>>>(w2);
    combine_kernel<<<T_TOKENS, 256>>>(x, out);
}

// round 6
// speedup vs baseline: 7.2230x; 2.1173x over previous
#include <cuda_runtime.h>
#include <cuda_fp16.h>
#include <cstdint>
#include <math.h>

// Problem constants
#define T_TOKENS 1024
#define HID      2048
#define INTER    1024
#define NR       32
#define ETOT     40
#define TOPK     4
#define MAXP     (T_TOKENS * TOPK)
#define RSF      1.0f

#define CH1      (HID / 32)     // 64 K-chunks (chunk K = 32) in stage 1
#define CH2      (INTER / 32)   // 32 K-chunks in stage 2
#define SMEM_SZ  33792          // 1KB meta + buffers (both stages)

// ---------------- device scratch ------------------------------------------
__device__ int   g_topk_id[T_TOKENS][TOPK];
__device__ float g_topk_w [T_TOKENS][TOPK];
__device__ float g_zero_sum[T_TOKENS];
__device__ int   g_counts [NR];
__device__ int   g_offsets[NR + 1];
__device__ int   g_pair_tok[MAXP];
__device__ float g_pair_w [MAXP];
__device__ int   g_tok_pair[T_TOKENS][TOPK];
__device__ __align__(16) __half g_xch[(size_t)T_TOKENS * HID];  // rn(x) fp16, 4MB
__device__ __align__(16) __half g_h  [(size_t)MAXP * INTER];    // rn(h) fp16, 8MB
__device__ __align__(16) float  g_ye [(size_t)MAXP * HID];      // weighted ye, 33.5MB

// ---------------- helpers --------------------------------------------------
__device__ __forceinline__ uint32_t smem_u32(const void* p) {
    uint32_t a;
    asm("{ .reg .u64 t; cvta.to.shared.u64 t, %1; cvt.u32.u64 %0, t; }"
        : "=r"(a) : "l"(p));
    return a;
}
__device__ __forceinline__ uint32_t h2u(__half2 h) {
    return *reinterpret_cast<uint32_t*>(&h);
}

__device__ __forceinline__ void mma_f16(float* d, const uint32_t* a, const uint32_t* b) {
    asm volatile(
        "mma.sync.aligned.m16n8k16.row.col.f32.f16.f16.f32 "
        "{%0,%1,%2,%3}, {%4,%5,%6,%7}, {%8,%9}, {%0,%1,%2,%3};"
        : "+f"(d[0]), "+f"(d[1]), "+f"(d[2]), "+f"(d[3])
        : "r"(a[0]), "r"(a[1]), "r"(a[2]), "r"(a[3]), "r"(b[0]), "r"(b[1]));
}
#define LDSM4(R, addr) \
    asm volatile("ldmatrix.sync.aligned.m8n8.x4.shared.b16 {%0,%1,%2,%3}, [%4];" \
        : "=r"((R)[0]), "=r"((R)[1]), "=r"((R)[2]), "=r"((R)[3]) : "r"(addr))
#define LDSM2(R, addr) \
    asm volatile("ldmatrix.sync.aligned.m8n8.x2.shared.b16 {%0,%1}, [%2];" \
        : "=r"((R)[0]), "=r"((R)[1]) : "r"(addr))

// ---------------- kernel 0: convert x to fp16 + zero state ----------------
__global__ void conv_x_kernel(const float* __restrict__ x) {
    int gi = blockIdx.x * 256 + threadIdx.x;
    int i = gi * 4;
    float4 v = *(const float4*)(x + i);
    __half2 p0 = __floats2half2_rn(v.x, v.y);
    __half2 p1 = __floats2half2_rn(v.z, v.w);
    uint2 o; o.x = h2u(p0); o.y = h2u(p1);
    *(uint2*)(g_xch + i) = o;
    if (gi < MAXP) ((int*)g_tok_pair)[gi] = -1;
    if (gi >= MAXP && gi < MAXP + NR) g_counts[gi - MAXP] = 0;
}

// ---------------- kernel 1: router (fp32) ---------------------------------
__global__ void __launch_bounds__(128) router_kernel(
    const float* __restrict__ x, const float* __restrict__ rw,
    const float* __restrict__ bias)
{
    int t = blockIdx.x;
    __shared__ float s_logit[ETOT];
    int tid = threadIdx.x;
    int warp = tid >> 5, lane = tid & 31;
    const float* xr = x + (size_t)t * HID;
    for (int e = warp; e < ETOT; e += 4) {
        const float* wr = rw + (size_t)e * HID;
        float acc = 0.f;
        #pragma unroll 4
        for (int j = lane; j < HID; j += 32) acc += xr[j] * wr[j];
        #pragma unroll
        for (int o = 16; o; o >>= 1) acc += __shfl_xor_sync(0xffffffffu, acc, o);
        if (lane == 0) s_logit[e] = acc;
    }
    __syncthreads();
    if (tid == 0) {
        float score[ETOT], sel[ETOT];
        for (int e = 0; e < ETOT; e++) {
            float s = 1.f / (1.f + expf(-s_logit[e]));
            score[e] = s;
            sel[e] = s + bias[e];
        }
        float zsum = 0.f;
        for (int k = 0; k < TOPK; k++) {
            int best = -1; float bv = -1e30f;
            for (int e = 0; e < ETOT; e++)
                if (sel[e] > bv) { bv = sel[e]; best = e; }
            sel[best] = -1e30f;
            if (best < NR) {
                g_topk_id[t][k] = best;
                g_topk_w[t][k]  = score[best];
                atomicAdd(&g_counts[best], 1);
            } else {
                g_topk_id[t][k] = -1;
                g_topk_w[t][k]  = 0.f;
                zsum += score[best];
            }
        }
        g_zero_sum[t] = zsum;
    }
}

// ---------------- kernel 2: compaction (with fused offsets scan) ----------
__global__ void __launch_bounds__(1024) scatter_kernel() {
    int e = blockIdx.x;
    int t = threadIdx.x;
    __shared__ int s_cnt[NR];
    if (t < NR) s_cnt[t] = g_counts[t];

    float w = 0.f; int flag = 0; int kmatch = 0;
    #pragma unroll
    for (int k = 0; k < TOPK; k++)
        if (g_topk_id[t][k] == e) { flag = 1; w = g_topk_w[t][k]; kmatch = k; }

    __shared__ int warp_sums[32];
    int lane = t & 31, wid = t >> 5;
    int v = flag;
    #pragma unroll
    for (int o = 1; o < 32; o <<= 1) {
        int n = __shfl_up_sync(0xffffffffu, v, o);
        if (lane >= o) v += n;
    }
    if (lane == 31) warp_sums[wid] = v;
    __syncthreads();
    if (wid == 0) {
        int s = warp_sums[lane];
        #pragma unroll
        for (int o = 1; o < 32; o <<= 1) {
            int n = __shfl_up_sync(0xffffffffu, s, o);
            if (lane >= o) s += n;
        }
        warp_sums[lane] = s;
    }
    __syncthreads();
    int off = 0;
    for (int i = 0; i < e; i++) off += s_cnt[i];
    if (t == 0) {
        g_offsets[e] = off;
        if (e == NR - 1) g_offsets[NR] = off + s_cnt[e];
    }
    int incl = v + (wid > 0 ? warp_sums[wid - 1] : 0);
    if (flag) {
        int idx = off + incl - 1;
        g_pair_tok[idx] = t;
        g_pair_w[idx]   = w;
        g_tok_pair[t][kmatch] = idx;
    }
}

// ============ SMEM layout: natural row-major half tiles, 64B rows ==========
// swizzle: 16B-column index ^= (row>>1)&3  → conflict-free STS.128/64 + LDSM

// ---------------- kernel 3: stage 1 (x@w1g, x@w1u, SwiGLU) -----------------
// CTA tile: 128 gathered tokens x 64 inter cols; warps 4(m) x 2(n).
__global__ void __launch_bounds__(256) stage1_kernel(
    const float* __restrict__ w1g, const float* __restrict__ w1u)
{
    int e   = blockIdx.y;
    int off = g_offsets[e];
    int cnt = g_offsets[e + 1] - off;
    int m0  = blockIdx.z * 128;
    if (m0 >= cnt) return;
    int i0 = blockIdx.x * 64;

    extern __shared__ __align__(16) char smem[];
    int* s_tok = (int*)smem;
    char* Abuf = smem + 1024;            // 2 x 8192 (128 rows x 64B)
    char* Gbuf = smem + 1024 + 16384;    // 2 x 4096 (64 rows x 64B)
    char* Ubuf = smem + 1024 + 24576;    // 2 x 4096
    uint32_t sbase = smem_u32(smem);
    uint32_t aA = sbase + 1024, aG = aA + 16384, aU = aG + 8192;

    int tid = threadIdx.x, lane = tid & 31, wid = tid >> 5;
    int wm = wid >> 1, wn = wid & 1;
    if (tid < 128) {
        int m = m0 + tid;
        s_tok[tid] = (m < cnt) ? g_pair_tok[off + m] : -1;
    }
    __syncthreads();

    // per-lane ldmatrix address components
    int lrow = lane & 7;
    int asel = lane >> 3;
    int arow = ((asel & 1) << 3) | lrow;      // row offset within m16 tile
    int ahi  = asel >> 1;                     // k-half select
    int aswz = (arow >> 1) & 3;
    int bhi  = (lane >> 3) & 1;
    int bswz = (lrow >> 1) & 3;

    const float* gbase = w1g + ((size_t)e * INTER + i0) * HID;
    const float* ubase = w1u + ((size_t)e * INTER + i0) * HID;

    float accG[2][4][4], accU[2][4][4];
    #pragma unroll
    for (int a = 0; a < 2; a++)
        #pragma unroll
        for (int b = 0; b < 4; b++)
            #pragma unroll
            for (int c = 0; c < 4; c++) { accG[a][b][c] = 0.f; accU[a][b][c] = 0.f; }

    uint4 rxa[2]; float4 rg[2], ru[2];
    auto ldg_chunk = [&](int it) {
        int k0 = it * 32;
        #pragma unroll
        for (int i = 0; i < 2; i++) {
            int idx = tid + i * 256; int r = idx >> 2, q = idx & 3;
            int tok = s_tok[r];
            rxa[i] = (tok >= 0) ? *(const uint4*)(g_xch + (size_t)tok * HID + k0 + q * 8)
                                : make_uint4(0u, 0u, 0u, 0u);
        }
        #pragma unroll
        for (int i = 0; i < 2; i++) {
            int idx = tid + i * 256; int r = idx >> 3, q = idx & 7;
            size_t go = (size_t)r * HID + k0 + q * 4;
            rg[i] = *(const float4*)(gbase + go);
            ru[i] = *(const float4*)(ubase + go);
        }
    };
    auto sts_chunk = [&](int buf) {
        char* A = Abuf + buf * 8192;
        char* G = Gbuf + buf * 4096;
        char* U = Ubuf + buf * 4096;
        #pragma unroll
        for (int i = 0; i < 2; i++) {
            int idx = tid + i * 256; int r = idx >> 2, q = idx & 3;
            *(uint4*)(A + r * 64 + ((q ^ ((r >> 1) & 3)) << 4)) = rxa[i];
        }
        #pragma unroll
        for (int i = 0; i < 2; i++) {
            int idx = tid + i * 256; int r = idx >> 3, q = idx & 7;
            int so = r * 64 + ((((q >> 1) ^ ((r >> 1) & 3)) << 4) | ((q & 1) << 3));
            uint2 vg; vg.x = h2u(__floats2half2_rn(rg[i].x, rg[i].y));
                      vg.y = h2u(__floats2half2_rn(rg[i].z, rg[i].w));
            *(uint2*)(G + so) = vg;
            uint2 vu; vu.x = h2u(__floats2half2_rn(ru[i].x, ru[i].y));
                      vu.y = h2u(__floats2half2_rn(ru[i].z, ru[i].w));
            *(uint2*)(U + so) = vu;
        }
    };
    auto compute = [&](int buf) {
        uint32_t bA = aA + buf * 8192;
        uint32_t bG = aG + buf * 4096;
        uint32_t bU = aU + buf * 4096;
        #pragma unroll
        for (int s = 0; s < 2; s++) {
            uint32_t af[2][4];
            int ac = (((2 * s + ahi) ^ aswz) << 4) + arow * 64;
            LDSM4(af[0], bA + (wm * 2)     * 1024 + ac);
            LDSM4(af[1], bA + (wm * 2 + 1) * 1024 + ac);
            int bc = (((2 * s + bhi) ^ bswz) << 4) + lrow * 64;
            #pragma unroll
            for (int t = 0; t < 4; t++) {
                int nt = wn * 4 + t;
                uint32_t bg[2], bu[2];
                LDSM2(bg, bG + nt * 512 + bc);
                LDSM2(bu, bU + nt * 512 + bc);
                mma_f16(accG[0][t], af[0], bg);
                mma_f16(accG[1][t], af[1], bg);
                mma_f16(accU[0][t], af[0], bu);
                mma_f16(accU[1][t], af[1], bu);
            }
        }
    };

    ldg_chunk(0); sts_chunk(0);
    __syncthreads();
    for (int it = 0; it < CH1; ++it) {
        bool pf = (it + 1) < CH1;
        if (pf) ldg_chunk(it + 1);
        compute(it & 1);
        if (pf) sts_chunk((it + 1) & 1);
        __syncthreads();
    }

    // epilogue: h = silu(g)*u -> fp16 g_h
    #pragma unroll
    for (int mi = 0; mi < 2; mi++) {
        int rbase = wm * 32 + mi * 16 + (lane >> 2);
        #pragma unroll
        for (int t = 0; t < 4; t++) {
            int col = i0 + wn * 32 + t * 8 + (lane & 3) * 2;
            #pragma unroll
            for (int half = 0; half < 2; half++) {
                int rloc = rbase + half * 8;
                int m = m0 + rloc;
                if (m < cnt) {
                    float g0 = accG[mi][t][half * 2],     u0 = accU[mi][t][half * 2];
                    float g1 = accG[mi][t][half * 2 + 1], u1 = accU[mi][t][half * 2 + 1];
                    float h0 = (g0 / (1.f + __expf(-g0))) * u0;
                    float h1 = (g1 / (1.f + __expf(-g1))) * u1;
                    *(__half2*)(g_h + (size_t)(off + m) * INTER + col) =
                        __floats2half2_rn(h0, h1);
                }
            }
        }
    }
}

// ---------------- kernel 4: stage 2 (h @ w2, weighted) ---------------------
// CTA tile: 128 pairs x 128 hidden cols; warps 4(m) x 2(n).
__global__ void __launch_bounds__(256) stage2_kernel(const float* __restrict__ w2)
{
    int e   = blockIdx.y;
    int off = g_offsets[e];
    int cnt = g_offsets[e + 1] - off;
    int m0  = blockIdx.z * 128;
    if (m0 >= cnt) return;
    int n0 = blockIdx.x * 128;

    extern __shared__ __align__(16) char smem[];
    float* s_w = (float*)smem;
    char* Abuf = smem + 1024;            // 2 x 8192
    char* Bbuf = smem + 1024 + 16384;    // 2 x 8192 (128 n-rows x 64B)
    uint32_t sbase = smem_u32(smem);
    uint32_t aA = sbase + 1024, aB = aA + 16384;

    int tid = threadIdx.x, lane = tid & 31, wid = tid >> 5;
    int wm = wid >> 1, wn = wid & 1;
    if (tid < 128) {
        int m = m0 + tid;
        s_w[tid] = (m < cnt) ? g_pair_w[off + m] : 0.f;
    }
    __syncthreads();

    int lrow = lane & 7;
    int asel = lane >> 3;
    int arow = ((asel & 1) << 3) | lrow;
    int ahi  = asel >> 1;
    int aswz = (arow >> 1) & 3;
    int bhi  = (lane >> 3) & 1;
    int bswz = (lrow >> 1) & 3;

    const float* bbase = w2 + ((size_t)e * HID + n0) * INTER;

    float acc[2][8][4];
    #pragma unroll
    for (int a = 0; a < 2; a++)
        #pragma unroll
        for (int b = 0; b < 8; b++)
            #pragma unroll
            for (int c = 0; c < 4; c++) acc[a][b][c] = 0.f;

    uint4 rxa[2]; float4 rb[4];
    auto ldg_chunk = [&](int it) {
        int k0 = it * 32;
        #pragma unroll
        for (int i = 0; i < 2; i++) {
            int idx = tid + i * 256; int r = idx >> 2, q = idx & 3;
            int m = m0 + r;
            rxa[i] = (m < cnt) ? *(const uint4*)(g_h + (size_t)(off + m) * INTER + k0 + q * 8)
                               : make_uint4(0u, 0u, 0u, 0u);
        }
        #pragma unroll
        for (int i = 0; i < 4; i++) {
            int idx = tid + i * 256; int r = idx >> 3, q = idx & 7;
            rb[i] = *(const float4*)(bbase + (size_t)r * INTER + k0 + q * 4);
        }
    };
    auto sts_chunk = [&](int buf) {
        char* A = Abuf + buf * 8192;
        char* B = Bbuf + buf * 8192;
        #pragma unroll
        for (int i = 0; i < 2; i++) {
            int idx = tid + i * 256; int r = idx >> 2, q = idx & 3;
            *(uint4*)(A + r * 64 + ((q ^ ((r >> 1) & 3)) << 4)) = rxa[i];
        }
        #pragma unroll
        for (int i = 0; i < 4; i++) {
            int idx = tid + i * 256; int r = idx >> 3, q = idx & 7;
            int so = r * 64 + ((((q >> 1) ^ ((r >> 1) & 3)) << 4) | ((q & 1) << 3));
            uint2 vb; vb.x = h2u(__floats2half2_rn(rb[i].x, rb[i].y));
                      vb.y = h2u(__floats2half2_rn(rb[i].z, rb[i].w));
            *(uint2*)(B + so) = vb;
        }
    };
    auto compute = [&](int buf) {
        uint32_t bA = aA + buf * 8192;
        uint32_t bB = aB + buf * 8192;
        #pragma unroll
        for (int s = 0; s < 2; s++) {
            uint32_t af[2][4];
            int ac = (((2 * s + ahi) ^ aswz) << 4) + arow * 64;
            LDSM4(af[0], bA + (wm * 2)     * 1024 + ac);
            LDSM4(af[1], bA + (wm * 2 + 1) * 1024 + ac);
            int bc = (((2 * s + bhi) ^ bswz) << 4) + lrow * 64;
            #pragma unroll
            for (int t = 0; t < 8; t++) {
                int nt = wn * 8 + t;
                uint32_t bf[2];
                LDSM2(bf, bB + nt * 512 + bc);
                mma_f16(acc[0][t], af[0], bf);
                mma_f16(acc[1][t], af[1], bf);
            }
        }
    };

    ldg_chunk(0); sts_chunk(0);
    __syncthreads();
    for (int it = 0; it < CH2; ++it) {
        bool pf = (it + 1) < CH2;
        if (pf) ldg_chunk(it + 1);
        compute(it & 1);
        if (pf) sts_chunk((it + 1) & 1);
        __syncthreads();
    }

    // epilogue: weighted rows into g_ye (fp32)
    #pragma unroll
    for (int mi = 0; mi < 2; mi++) {
        int rbase = wm * 32 + mi * 16 + (lane >> 2);
        #pragma unroll
        for (int t = 0; t < 8; t++) {
            int col = n0 + wn * 64 + t * 8 + (lane & 3) * 2;
            #pragma unroll
            for (int half = 0; half < 2; half++) {
                int rloc = rbase + half * 8;
                int m = m0 + rloc;
                if (m < cnt) {
                    float pw = s_w[rloc];
                    float2 o;
                    o.x = pw * acc[mi][t][half * 2];
                    o.y = pw * acc[mi][t][half * 2 + 1];
                    *(float2*)(g_ye + (size_t)(off + m) * HID + col) = o;
                }
            }
        }
    }
}

// ---------------- kernel 5: combine ---------------------------------------
__global__ void __launch_bounds__(256) combine_kernel(
    const float* __restrict__ x, float* __restrict__ out)
{
    int t = blockIdx.x;
    int c = threadIdx.x * 8;
    float zs = g_zero_sum[t];
    const float* xr = x + (size_t)t * HID + c;
    float4 a0 = *(const float4*)xr;
    float4 a1 = *(const float4*)(xr + 4);
    a0.x *= zs; a0.y *= zs; a0.z *= zs; a0.w *= zs;
    a1.x *= zs; a1.y *= zs; a1.z *= zs; a1.w *= zs;
    #pragma unroll
    for (int k = 0; k < TOPK; k++) {
        int p = g_tok_pair[t][k];
        if (p >= 0) {
            const float* yr = g_ye + (size_t)p * HID + c;
            float4 y0 = *(const float4*)yr;
            float4 y1 = *(const float4*)(yr + 4);
            a0.x += y0.x; a0.y += y0.y; a0.z += y0.z; a0.w += y0.w;
            a1.x += y1.x; a1.y += y1.y; a1.z += y1.z; a1.w += y1.w;
        }
    }
    a0.x *= RSF; a0.y *= RSF; a0.z *= RSF; a0.w *= RSF;
    a1.x *= RSF; a1.y *= RSF; a1.z *= RSF; a1.w *= RSF;
    float* o = out + (size_t)t * HID + c;
    *(float4*)o = a0;
    *(float4*)(o + 4) = a1;
}

// ---------------- launch ---------------------------------------------------
extern "C" void kernel_launch(void* const* d_in, const int* in_sizes, int n_in,
                              void* d_out, int out_size)
{
    const float* x    = (const float*)d_in[0];
    const float* rw   = (const float*)d_in[1];
    const float* bias = (const float*)d_in[2];
    const float* w1g  = (const float*)d_in[3];
    const float* w1u  = (const float*)d_in[4];
    const float* w2   = (const float*)d_in[5];
    float* out = (float*)d_out;

    cudaFuncSetAttribute(stage1_kernel, cudaFuncAttributeMaxDynamicSharedMemorySize, SMEM_SZ);
    cudaFuncSetAttribute(stage2_kernel, cudaFuncAttributeMaxDynamicSharedMemorySize, SMEM_SZ);

    conv_x_kernel<<<(T_TOKENS * HID) / (256 * 4), 256>>>(x);
    router_kernel<<<T_TOKENS, 128>>>(x, rw, bias);
    scatter_kernel<<<NR, 1024>>>();
    stage1_kernel<<<dim3(INTER / 64, NR, 8), 256, SMEM_SZ>>>(w1g, w1u);
    stage2_kernel<<<dim3(HID / 128, NR, 8), 256, SMEM_SZ>>>(w2);
    combine_kernel<<<T_TOKENS, 256>>>(x, out);
}